// round 2
// baseline (speedup 1.0000x reference)
#include <cuda_runtime.h>
#include <cstdint>

// ---------------------------------------------------------------------------
// GumbelVectorQuantizer forward, GB300.
// B=8, T=2048, D=1024, V=16, K=512, d=64.
// Outputs (float32, concatenated): quantized (8*2048*1024), targets (8*2048),
// losses (1). Total 16793601 floats.
// ---------------------------------------------------------------------------

#define BB   8
#define TT   2048
#define DD   1024
#define VV   16
#define KK   512
#define DG   64
#define MROWS (BB * TT)          // 16384

#define OUT_QUANT   0
#define OUT_TARGETS (MROWS * DD)            // 16777216
#define OUT_LOSS    (MROWS * DD + MROWS)    // 16793600

// Scratch (device globals: allocation-free contract)
__device__ float g_Q[MROWS * DD];    // q = features @ Wq^T + bq
__device__ float g_G[MROWS * DD];    // gathered codebook rows
__device__ int   g_idx[MROWS * VV];  // argmax indices
__device__ int   g_counts[VV * KK];  // codebook usage counts

// ---------------------------------------------------------------------------
// Threefry2x32, JAX partitionable path, key = (0, 42).
// For flat element index i (< 2^32): counter u64 = i -> (hi=0, lo=i).
// bits = out0 ^ out1 of threefry2x32(key, (0, i)).
// ---------------------------------------------------------------------------
__device__ __forceinline__ uint32_t rotl32(uint32_t x, int r) {
    return __funnelshift_l(x, x, r);
}
__device__ __forceinline__ void tf_round(uint32_t& x0, uint32_t& x1, int r) {
    x0 += x1;
    x1 = rotl32(x1, r);
    x1 ^= x0;
}
__device__ __forceinline__ uint32_t tf_bits(uint32_t i) {
    const uint32_t ks0 = 0u;
    const uint32_t ks1 = 42u;
    const uint32_t ks2 = 0x1BD11BDAu ^ ks0 ^ ks1;
    uint32_t x0 = 0u + ks0;   // counter hi = 0
    uint32_t x1 = i + ks1;    // counter lo = i
    tf_round(x0, x1, 13); tf_round(x0, x1, 15); tf_round(x0, x1, 26); tf_round(x0, x1, 6);
    x0 += ks1; x1 += ks2 + 1u;
    tf_round(x0, x1, 17); tf_round(x0, x1, 29); tf_round(x0, x1, 16); tf_round(x0, x1, 24);
    x0 += ks2; x1 += ks0 + 2u;
    tf_round(x0, x1, 13); tf_round(x0, x1, 15); tf_round(x0, x1, 26); tf_round(x0, x1, 6);
    x0 += ks0; x1 += ks1 + 3u;
    tf_round(x0, x1, 17); tf_round(x0, x1, 29); tf_round(x0, x1, 16); tf_round(x0, x1, 24);
    x0 += ks1; x1 += ks2 + 4u;
    tf_round(x0, x1, 13); tf_round(x0, x1, 15); tf_round(x0, x1, 26); tf_round(x0, x1, 6);
    x0 += ks2; x1 += ks0 + 5u;
    return x0 ^ x1;
}

__device__ __forceinline__ float gumbel_from_bits(uint32_t r) {
    // JAX uniform [0,1): bitcast((bits>>9)|0x3f800000) - 1
    float u = __uint_as_float((r >> 9) | 0x3f800000u) - 1.0f;
    // gumbel = -log(-log(u + eps) + eps)   (accurate logf: argmax-critical)
    return -logf(-logf(u + 1e-8f) + 1e-8f);
}

// ---------------------------------------------------------------------------
// SGEMM: C[M][1024] = A[M][1024] @ W[1024][1024]^T + bias
// BM=BN=128, BK=8, 256 threads, 8x8 per thread.
// ---------------------------------------------------------------------------
__global__ __launch_bounds__(256, 2)
void sgemm_bt(const float* __restrict__ A, const float* __restrict__ W,
              const float* __restrict__ bias, float* __restrict__ C) {
    __shared__ float As[8][128];
    __shared__ float Bs[8][128];

    const int tid = threadIdx.x;
    const int m0 = blockIdx.y * 128;
    const int n0 = blockIdx.x * 128;

    const int loadRow = tid >> 1;          // 0..127
    const int loadCol = (tid & 1) << 2;    // 0 or 4
    const int tx = tid & 15;               // 0..15
    const int ty = tid >> 4;               // 0..15

    float acc[8][8];
#pragma unroll
    for (int i = 0; i < 8; i++)
#pragma unroll
        for (int j = 0; j < 8; j++) acc[i][j] = 0.0f;

    const float* Aptr = A + (size_t)(m0 + loadRow) * DD + loadCol;
    const float* Wptr = W + (size_t)(n0 + loadRow) * DD + loadCol;

    for (int k0 = 0; k0 < DD; k0 += 8) {
        float4 av = *(const float4*)(Aptr + k0);
        float4 wv = *(const float4*)(Wptr + k0);
        __syncthreads();
        As[loadCol + 0][loadRow] = av.x;
        As[loadCol + 1][loadRow] = av.y;
        As[loadCol + 2][loadRow] = av.z;
        As[loadCol + 3][loadRow] = av.w;
        Bs[loadCol + 0][loadRow] = wv.x;
        Bs[loadCol + 1][loadRow] = wv.y;
        Bs[loadCol + 2][loadRow] = wv.z;
        Bs[loadCol + 3][loadRow] = wv.w;
        __syncthreads();
#pragma unroll
        for (int kk = 0; kk < 8; kk++) {
            float rm[8], rn[8];
            float4 a0 = *(const float4*)&As[kk][ty * 8 + 0];
            float4 a1 = *(const float4*)&As[kk][ty * 8 + 4];
            float4 b0 = *(const float4*)&Bs[kk][tx * 8 + 0];
            float4 b1 = *(const float4*)&Bs[kk][tx * 8 + 4];
            rm[0] = a0.x; rm[1] = a0.y; rm[2] = a0.z; rm[3] = a0.w;
            rm[4] = a1.x; rm[5] = a1.y; rm[6] = a1.z; rm[7] = a1.w;
            rn[0] = b0.x; rn[1] = b0.y; rn[2] = b0.z; rn[3] = b0.w;
            rn[4] = b1.x; rn[5] = b1.y; rn[6] = b1.z; rn[7] = b1.w;
#pragma unroll
            for (int i = 0; i < 8; i++)
#pragma unroll
                for (int j = 0; j < 8; j++)
                    acc[i][j] = fmaf(rm[i], rn[j], acc[i][j]);
        }
    }

    // epilogue with bias
#pragma unroll
    for (int i = 0; i < 8; i++) {
        const int row = m0 + ty * 8 + i;
        float* crow = C + (size_t)row * DD + n0 + tx * 8;
        const float* brow = bias + n0 + tx * 8;
        float4 o0, o1;
        o0.x = acc[i][0] + brow[0]; o0.y = acc[i][1] + brow[1];
        o0.z = acc[i][2] + brow[2]; o0.w = acc[i][3] + brow[3];
        o1.x = acc[i][4] + brow[4]; o1.y = acc[i][5] + brow[5];
        o1.z = acc[i][6] + brow[6]; o1.w = acc[i][7] + brow[7];
        *(float4*)(crow + 0) = o0;
        *(float4*)(crow + 4) = o1;
    }
}

// ---------------------------------------------------------------------------
// Fused: distances + gumbel + argmax + gather + counts
// grid (V=16, 19), block 512. Codebook[v] resident in smem, transposed [d][k].
// ---------------------------------------------------------------------------
#define SM_CB   0                    // 64*512 floats
#define SM_C2   (64 * 512)           // 512
#define SM_QS   (SM_C2 + 512)        // 512  (8 b * 64 d)
#define SM_Q2   (SM_QS + 512)        // 16 (8 used)
#define SM_SC   (SM_Q2 + 16)         // 8*512 scores
#define SM_TOT  (SM_SC + 8 * 512)    // 37904 floats = 151616 bytes

__global__ __launch_bounds__(512, 1)
void fused_vq(const float* __restrict__ Q, const float* __restrict__ cbk,
              float* __restrict__ G, int* __restrict__ idxOut,
              int* __restrict__ counts) {
    extern __shared__ float sm[];
    float* cb  = sm + SM_CB;   // [64][512]: cb[d*512+k] = codebooks[v][k][d]
    float* c2s = sm + SM_C2;
    float* qs  = sm + SM_QS;
    float* q2s = sm + SM_Q2;
    float* scs = sm + SM_SC;

    const int v    = blockIdx.x;
    const int tid  = threadIdx.x;
    const int lane = tid & 31;
    const int w    = tid >> 5;
    const int k    = tid;      // this thread's codebook entry

    // Load codebook[v] transposed into smem (coalesced gmem reads)
    const float4* cbg = (const float4*)(cbk + (size_t)v * KK * DG);
    for (int i = tid; i < KK * 16; i += 512) {
        // i = k_*16 + d4  -> gmem float4 index i (fully coalesced)
        int d4 = i & 15;
        int kq = i >> 4;
        float4 val = cbg[i];
        cb[(d4 * 4 + 0) * KK + kq] = val.x;
        cb[(d4 * 4 + 1) * KK + kq] = val.y;
        cb[(d4 * 4 + 2) * KK + kq] = val.z;
        cb[(d4 * 4 + 3) * KK + kq] = val.w;
    }
    __syncthreads();

    // c2[k] = sum_d cb[d][k]^2   (lanes span k -> conflict-free)
    {
        float s = 0.0f;
#pragma unroll 16
        for (int d = 0; d < DG; d++) {
            float c = cb[d * KK + k];
            s = fmaf(c, c, s);
        }
        c2s[k] = s;
    }

    for (int t = blockIdx.y; t < TT; t += gridDim.y) {
        __syncthreads();
        // load q rows for all 8 batches: qs[b*64+d]
        {
            int b = tid >> 6, dd = tid & 63;
            qs[tid] = Q[(size_t)(b * TT + t) * DD + v * DG + dd];
        }
        __syncthreads();
        // q2 per batch (warps 0..7)
        if (w < 8) {
            float a = qs[w * 64 + lane];
            float b2 = qs[w * 64 + 32 + lane];
            float ss = a * a + b2 * b2;
#pragma unroll
            for (int o = 16; o; o >>= 1) ss += __shfl_xor_sync(0xffffffffu, ss, o);
            if (lane == 0) q2s[w] = ss;
        }
        __syncthreads();

        // dot products: acc[b] = q[b] . codebook[v][k]
        float acc[8];
#pragma unroll
        for (int b = 0; b < 8; b++) acc[b] = 0.0f;
#pragma unroll
        for (int d4 = 0; d4 < 16; d4++) {
            float c0 = cb[(d4 * 4 + 0) * KK + k];
            float c1 = cb[(d4 * 4 + 1) * KK + k];
            float c2 = cb[(d4 * 4 + 2) * KK + k];
            float c3 = cb[(d4 * 4 + 3) * KK + k];
#pragma unroll
            for (int b = 0; b < 8; b++) {
                float4 qv = *(const float4*)(qs + b * 64 + d4 * 4);
                float s = acc[b];
                s = fmaf(qv.x, c0, s);
                s = fmaf(qv.y, c1, s);
                s = fmaf(qv.z, c2, s);
                s = fmaf(qv.w, c3, s);
                acc[b] = s;
            }
        }

        const float c2k = c2s[k];
        const uint32_t base = (uint32_t)t * 8192u + (uint32_t)v * 512u + (uint32_t)k;
        // scores = gumbel - dist  (argmax-equivalent to softmax((logits+g)/T))
#pragma unroll
        for (int b = 0; b < 8; b++) {
            uint32_t bits = tf_bits(base + (uint32_t)b * 16777216u);
            float d0 = sqrtf(fmaxf(q2s[b] + c2k - 2.0f * acc[b], 0.0f));
            scs[b * KK + k] = gumbel_from_bits(bits) - d0;
        }
        __syncthreads();

        // argmax per batch (warps 0..7), first-index tie-break
        if (w < 8) {
            const int b = w;
            float best = -3.4e38f;
            int bi = 0;
            for (int i = lane; i < KK; i += 32) {
                float s = scs[b * KK + i];
                if (s > best) { best = s; bi = i; }
            }
#pragma unroll
            for (int o = 16; o; o >>= 1) {
                float ob = __shfl_down_sync(0xffffffffu, best, o);
                int   oi = __shfl_down_sync(0xffffffffu, bi, o);
                if (ob > best || (ob == best && oi < bi)) { best = ob; bi = oi; }
            }
            bi = __shfl_sync(0xffffffffu, bi, 0);

            // gather winning codebook row from gmem (L2-resident, coalesced)
            const float* crow = cbk + ((size_t)v * KK + bi) * DG;
            float* grow = G + (size_t)(b * TT + t) * DD + v * DG;
            grow[lane]      = crow[lane];
            grow[lane + 32] = crow[lane + 32];
            if (lane == 0) {
                idxOut[(b * TT + t) * VV + v] = bi;
                atomicAdd(&counts[v * KK + bi], 1);
            }
        }
    }
}

// ---------------------------------------------------------------------------
// Small kernels
// ---------------------------------------------------------------------------
__global__ void zero_counts_k(int* __restrict__ counts) {
    int i = blockIdx.x * blockDim.x + threadIdx.x;
    if (i < VV * KK) counts[i] = 0;
}

__global__ void targets_k(const int* __restrict__ idxIn, float* __restrict__ out) {
    int i = blockIdx.x * blockDim.x + threadIdx.x;
    if (i < MROWS) {
        int s = 0;
#pragma unroll
        for (int v = 0; v < VV; v++) s += idxIn[i * VV + v] * (v * KK);
        out[OUT_TARGETS + i] = (float)s;
    }
}

__global__ void loss_k(const int* __restrict__ counts, float* __restrict__ out) {
    __shared__ float ent_s[VV];
    const int tid = threadIdx.x, lane = tid & 31, w = tid >> 5;
    if (w < VV) {
        float tot = 0.0f;
        for (int kk = lane; kk < KK; kk += 32) tot += (float)counts[w * KK + kk];
#pragma unroll
        for (int o = 16; o; o >>= 1) tot += __shfl_xor_sync(0xffffffffu, tot, o);
        float inv = 1.0f / tot;   // tot = 16384 -> exact
        float pl = 0.0f;
        for (int kk = lane; kk < KK; kk += 32) {
            float p = (float)counts[w * KK + kk] * inv;
            pl += p * logf(p + 1e-8f);
        }
#pragma unroll
        for (int o = 16; o; o >>= 1) pl += __shfl_xor_sync(0xffffffffu, pl, o);
        if (lane == 0) ent_s[w] = -pl;
    }
    __syncthreads();
    if (tid == 0) {
        float lk = logf(512.0f);
        float acc = 0.0f;
#pragma unroll
        for (int v = 0; v < VV; v++) acc += ent_s[v] / lk;
        float diversity = -(acc / (float)VV);
        out[OUT_LOSS] = 0.1f * diversity;
    }
}

// ---------------------------------------------------------------------------
// Launch
// ---------------------------------------------------------------------------
extern "C" void kernel_launch(void* const* d_in, const int* in_sizes, int n_in,
                              void* d_out, int out_size) {
    const float* features  = (const float*)d_in[0];
    const float* codebooks = (const float*)d_in[1];
    const float* Wq        = (const float*)d_in[2];
    const float* bq        = (const float*)d_in[3];
    const float* Wout      = (const float*)d_in[4];
    const float* bout      = (const float*)d_in[5];
    float* out = (float*)d_out;

    float* Qb;  cudaGetSymbolAddress((void**)&Qb,  g_Q);
    float* Gb;  cudaGetSymbolAddress((void**)&Gb,  g_G);
    int* idxP;  cudaGetSymbolAddress((void**)&idxP, g_idx);
    int* cntP;  cudaGetSymbolAddress((void**)&cntP, g_counts);

    const size_t fusedSmem = (size_t)SM_TOT * sizeof(float);
    cudaFuncSetAttribute(fused_vq, cudaFuncAttributeMaxDynamicSharedMemorySize,
                         (int)fusedSmem);

    zero_counts_k<<<16, 512>>>(cntP);
    sgemm_bt<<<dim3(8, 128), 256>>>(features, Wq, bq, Qb);
    fused_vq<<<dim3(VV, 19), 512, fusedSmem>>>(Qb, codebooks, Gb, idxP, cntP);
    sgemm_bt<<<dim3(8, 128), 256>>>(Gb, Wout, bout, out);
    targets_k<<<(MROWS + 255) / 256, 256>>>(idxP, out);
    loss_k<<<1, 512>>>(cntP, out);
}

// round 3
// speedup vs baseline: 1.3797x; 1.3797x over previous
#include <cuda_runtime.h>
#include <cstdint>

// ---------------------------------------------------------------------------
// GumbelVectorQuantizer forward, GB300.
// B=8, T=2048, D=1024, V=16, K=512, d=64.
// ---------------------------------------------------------------------------

#define BB   8
#define TT   2048
#define DD   1024
#define VV   16
#define KK   512
#define DG   64
#define MROWS (BB * TT)          // 16384

#define OUT_QUANT   0
#define OUT_TARGETS (MROWS * DD)            // 16777216
#define OUT_LOSS    (MROWS * DD + MROWS)    // 16793600

// Scratch (device globals: allocation-free contract)
__device__ float g_Q[MROWS * DD];    // q = features @ Wq^T + bq
__device__ float g_G[MROWS * DD];    // gathered codebook rows
__device__ int   g_idx[MROWS * VV];  // argmax indices
__device__ int   g_counts[VV * KK];  // codebook usage counts
__device__ float g_delta[VV];        // per-group safe score window

// ---------------------------------------------------------------------------
// Threefry2x32, JAX partitionable path, key = (0, 42).
// bits(i) = o0 ^ o1 of threefry2x32(key, (0, i)).
// ---------------------------------------------------------------------------
__device__ __forceinline__ uint32_t rotl32(uint32_t x, int r) {
    return __funnelshift_l(x, x, r);
}
__device__ __forceinline__ void tf_round(uint32_t& x0, uint32_t& x1, int r) {
    x0 += x1;
    x1 = rotl32(x1, r);
    x1 ^= x0;
}
__device__ __forceinline__ uint32_t tf_bits(uint32_t i) {
    const uint32_t ks0 = 0u;
    const uint32_t ks1 = 42u;
    const uint32_t ks2 = 0x1BD11BDAu ^ ks0 ^ ks1;
    uint32_t x0 = 0u + ks0;   // counter hi = 0
    uint32_t x1 = i + ks1;    // counter lo = i
    tf_round(x0, x1, 13); tf_round(x0, x1, 15); tf_round(x0, x1, 26); tf_round(x0, x1, 6);
    x0 += ks1; x1 += ks2 + 1u;
    tf_round(x0, x1, 17); tf_round(x0, x1, 29); tf_round(x0, x1, 16); tf_round(x0, x1, 24);
    x0 += ks2; x1 += ks0 + 2u;
    tf_round(x0, x1, 13); tf_round(x0, x1, 15); tf_round(x0, x1, 26); tf_round(x0, x1, 6);
    x0 += ks0; x1 += ks1 + 3u;
    tf_round(x0, x1, 17); tf_round(x0, x1, 29); tf_round(x0, x1, 16); tf_round(x0, x1, 24);
    x0 += ks1; x1 += ks2 + 4u;
    tf_round(x0, x1, 13); tf_round(x0, x1, 15); tf_round(x0, x1, 26); tf_round(x0, x1, 6);
    x0 += ks2; x1 += ks0 + 5u;
    return x0 ^ x1;
}

__device__ __forceinline__ float gumbel_from_ubits(uint32_t ub) {
    // u = bitcast(0x3f800000 | ubits) - 1  (== ubits * 2^-23 exactly)
    float u = __uint_as_float(0x3f800000u | ub) - 1.0f;
    return -logf(-logf(u + 1e-8f) + 1e-8f);
}

// ---------------------------------------------------------------------------
// SGEMM: C[M][1024] = A[M][1024] @ W[1024][1024]^T + bias
// ---------------------------------------------------------------------------
__global__ __launch_bounds__(256, 2)
void sgemm_bt(const float* __restrict__ A, const float* __restrict__ W,
              const float* __restrict__ bias, float* __restrict__ C) {
    __shared__ float As[8][128];
    __shared__ float Bs[8][128];

    const int tid = threadIdx.x;
    const int m0 = blockIdx.y * 128;
    const int n0 = blockIdx.x * 128;

    const int loadRow = tid >> 1;
    const int loadCol = (tid & 1) << 2;
    const int tx = tid & 15;
    const int ty = tid >> 4;

    float acc[8][8];
#pragma unroll
    for (int i = 0; i < 8; i++)
#pragma unroll
        for (int j = 0; j < 8; j++) acc[i][j] = 0.0f;

    const float* Aptr = A + (size_t)(m0 + loadRow) * DD + loadCol;
    const float* Wptr = W + (size_t)(n0 + loadRow) * DD + loadCol;

    for (int k0 = 0; k0 < DD; k0 += 8) {
        float4 av = *(const float4*)(Aptr + k0);
        float4 wv = *(const float4*)(Wptr + k0);
        __syncthreads();
        As[loadCol + 0][loadRow] = av.x;
        As[loadCol + 1][loadRow] = av.y;
        As[loadCol + 2][loadRow] = av.z;
        As[loadCol + 3][loadRow] = av.w;
        Bs[loadCol + 0][loadRow] = wv.x;
        Bs[loadCol + 1][loadRow] = wv.y;
        Bs[loadCol + 2][loadRow] = wv.z;
        Bs[loadCol + 3][loadRow] = wv.w;
        __syncthreads();
#pragma unroll
        for (int kk = 0; kk < 8; kk++) {
            float rm[8], rn[8];
            float4 a0 = *(const float4*)&As[kk][ty * 8 + 0];
            float4 a1 = *(const float4*)&As[kk][ty * 8 + 4];
            float4 b0 = *(const float4*)&Bs[kk][tx * 8 + 0];
            float4 b1 = *(const float4*)&Bs[kk][tx * 8 + 4];
            rm[0] = a0.x; rm[1] = a0.y; rm[2] = a0.z; rm[3] = a0.w;
            rm[4] = a1.x; rm[5] = a1.y; rm[6] = a1.z; rm[7] = a1.w;
            rn[0] = b0.x; rn[1] = b0.y; rn[2] = b0.z; rn[3] = b0.w;
            rn[4] = b1.x; rn[5] = b1.y; rn[6] = b1.z; rn[7] = b1.w;
#pragma unroll
            for (int i = 0; i < 8; i++)
#pragma unroll
                for (int j = 0; j < 8; j++)
                    acc[i][j] = fmaf(rm[i], rn[j], acc[i][j]);
        }
    }

#pragma unroll
    for (int i = 0; i < 8; i++) {
        const int row = m0 + ty * 8 + i;
        float* crow = C + (size_t)row * DD + n0 + tx * 8;
        const float* brow = bias + n0 + tx * 8;
        float4 o0, o1;
        o0.x = acc[i][0] + brow[0]; o0.y = acc[i][1] + brow[1];
        o0.z = acc[i][2] + brow[2]; o0.w = acc[i][3] + brow[3];
        o1.x = acc[i][4] + brow[4]; o1.y = acc[i][5] + brow[5];
        o1.z = acc[i][6] + brow[6]; o1.w = acc[i][7] + brow[7];
        *(float4*)(crow + 0) = o0;
        *(float4*)(crow + 4) = o1;
    }
}

// ---------------------------------------------------------------------------
// delta_k: per-v safe window  Delta_v = 2*max_k ||c_k|| + margin
// ---------------------------------------------------------------------------
__global__ void delta_k(const float* __restrict__ cbk, float* __restrict__ gd) {
    __shared__ float red[16];
    const int v = blockIdx.x;
    const int k = threadIdx.x;          // 512
    const int lane = k & 31, w = k >> 5;
    const float* crow = cbk + ((size_t)(v * KK + k)) * DG;
    float s = 0.0f;
#pragma unroll
    for (int d = 0; d < DG; d += 4) {
        float4 c = *(const float4*)(crow + d);
        s += c.x * c.x + c.y * c.y + c.z * c.z + c.w * c.w;
    }
#pragma unroll
    for (int o = 16; o; o >>= 1) s = fmaxf(s, __shfl_xor_sync(0xffffffffu, s, o));
    if (lane == 0) red[w] = s;
    __syncthreads();
    if (k == 0) {
        float m = 0.0f;
#pragma unroll
        for (int i = 0; i < 16; i++) m = fmaxf(m, red[i]);
        gd[v] = 2.0f * sqrtf(m) + 0.05f;
    }
}

// ---------------------------------------------------------------------------
// Fused: threefry bits -> integer argmax -> candidate window -> exact scores
// grid (T=2048), block 512 (one thread per k).
// ---------------------------------------------------------------------------
#define CAP 4096

__global__ __launch_bounds__(512, 2)
void fused_vq(const float* __restrict__ Q, const float* __restrict__ cbk,
              const float* __restrict__ gdelta,
              float* __restrict__ G, int* __restrict__ idxOut,
              int* __restrict__ counts) {
    __shared__ uint32_t ub[8][KK];         // ubits per (batch, k)
    __shared__ uint32_t cand[CAP];         // (b<<16)|k
    __shared__ int scnt;
    __shared__ unsigned long long sbest[8];
    __shared__ uint32_t sthr[8];

    const int t = blockIdx.x;
    const int tid = threadIdx.x;
    const int lane = tid & 31;
    const int w = tid >> 5;
    const int k = tid;

    for (int v = 0; v < VV; v++) {
        if (tid < 8) sbest[tid] = 0ull;
        if (tid == 0) scnt = 0;

        // 1) generate bits for all 8 batches at this (t, v, k)
        uint32_t r[8];
        const uint32_t base = (uint32_t)t * 8192u + (uint32_t)v * 512u + (uint32_t)k;
#pragma unroll
        for (int b = 0; b < 8; b++) {
            uint32_t bits = tf_bits(base + ((uint32_t)b << 24));
            r[b] = bits >> 9;
            ub[b][k] = r[b];
        }
        __syncthreads();

        // 2) integer max per batch -> gumbel of max -> ubits threshold
        if (w < 8) {
            uint32_t m = 0u;
#pragma unroll
            for (int j = 0; j < 16; j++) m = max(m, ub[w][lane + 32 * j]);
#pragma unroll
            for (int o = 16; o; o >>= 1)
                m = max(m, __shfl_xor_sync(0xffffffffu, m, o));
            if (lane == 0) {
                float gmax = gumbel_from_ubits(m);
                float glo = gmax - gdelta[v];
                // inverse gumbel: u_lo = exp(-(exp(-glo) - eps)) - eps
                float ulo = expf(-(expf(-glo) - 1e-8f)) - 1e-8f;
                int it = (int)floorf(ulo * 8388608.0f) - 16;   // safety margin
                sthr[w] = (uint32_t)max(it, 0);
            }
        }
        __syncthreads();

        // 3) collect candidates (usually 1 per (b,v))
#pragma unroll
        for (int b = 0; b < 8; b++) {
            if (r[b] >= sthr[b]) {
                int p = atomicAdd(&scnt, 1);
                cand[p] = ((uint32_t)b << 16) | (uint32_t)k;   // CAP==8*KK: no overflow
            }
        }
        __syncthreads();

        // 4) exact score for each candidate (one warp per candidate)
        const int n = scnt;
        for (int c = w; c < n; c += 16) {
            const uint32_t e = cand[c];
            const int b = (int)(e >> 16);
            const int kc = (int)(e & 0xffffu);
            const float* qrow = Q + ((size_t)(b * TT + t)) * DD + v * DG;
            const float* crow = cbk + ((size_t)(v * KK + kc)) * DG;
            float q0 = qrow[lane], q1 = qrow[lane + 32];
            float c0 = crow[lane], c1 = crow[lane + 32];
            float qc = q0 * c0 + q1 * c1;
            float q2 = q0 * q0 + q1 * q1;
            float c2 = c0 * c0 + c1 * c1;
#pragma unroll
            for (int o = 16; o; o >>= 1) {
                qc += __shfl_xor_sync(0xffffffffu, qc, o);
                q2 += __shfl_xor_sync(0xffffffffu, q2, o);
                c2 += __shfl_xor_sync(0xffffffffu, c2, o);
            }
            if (lane == 0) {
                float dist = sqrtf(fmaxf(q2 + c2 - 2.0f * qc, 0.0f));
                float g = gumbel_from_ubits(ub[b][kc]);
                float s = g - dist;   // argmax-equivalent to softmax((logit+g)/T)
                uint32_t sb = __float_as_uint(s);
                uint32_t os = (sb & 0x80000000u) ? ~sb : (sb | 0x80000000u);
                unsigned long long key =
                    ((unsigned long long)os << 32) | (uint32_t)(511 - kc);
                atomicMax(&sbest[b], key);   // ties -> smaller k wins
            }
        }
        __syncthreads();

        // 5) winners: write idx, counts, gather codebook row
        if (w < 8) {
            const int b = w;
            const int kw = 511 - (int)(sbest[b] & 0xffffffffu);
            const float* crow = cbk + ((size_t)(v * KK + kw)) * DG;
            float* grow = G + ((size_t)(b * TT + t)) * DD + v * DG;
            grow[lane]      = crow[lane];
            grow[lane + 32] = crow[lane + 32];
            if (lane == 0) {
                idxOut[(b * TT + t) * VV + v] = kw;
                atomicAdd(&counts[v * KK + kw], 1);
            }
        }
        __syncthreads();
    }
}

// ---------------------------------------------------------------------------
// Small kernels
// ---------------------------------------------------------------------------
__global__ void zero_counts_k(int* __restrict__ counts) {
    int i = blockIdx.x * blockDim.x + threadIdx.x;
    if (i < VV * KK) counts[i] = 0;
}

__global__ void targets_k(const int* __restrict__ idxIn, float* __restrict__ out) {
    int i = blockIdx.x * blockDim.x + threadIdx.x;
    if (i < MROWS) {
        int s = 0;
#pragma unroll
        for (int v = 0; v < VV; v++) s += idxIn[i * VV + v] * (v * KK);
        out[OUT_TARGETS + i] = (float)s;
    }
}

__global__ void loss_k(const int* __restrict__ counts, float* __restrict__ out) {
    __shared__ float ent_s[VV];
    const int tid = threadIdx.x, lane = tid & 31, w = tid >> 5;
    if (w < VV) {
        float tot = 0.0f;
        for (int kk = lane; kk < KK; kk += 32) tot += (float)counts[w * KK + kk];
#pragma unroll
        for (int o = 16; o; o >>= 1) tot += __shfl_xor_sync(0xffffffffu, tot, o);
        float inv = 1.0f / tot;
        float pl = 0.0f;
        for (int kk = lane; kk < KK; kk += 32) {
            float p = (float)counts[w * KK + kk] * inv;
            pl += p * logf(p + 1e-8f);
        }
#pragma unroll
        for (int o = 16; o; o >>= 1) pl += __shfl_xor_sync(0xffffffffu, pl, o);
        if (lane == 0) ent_s[w] = -pl;
    }
    __syncthreads();
    if (tid == 0) {
        float lk = logf(512.0f);
        float acc = 0.0f;
#pragma unroll
        for (int v = 0; v < VV; v++) acc += ent_s[v] / lk;
        float diversity = -(acc / (float)VV);
        out[OUT_LOSS] = 0.1f * diversity;
    }
}

// ---------------------------------------------------------------------------
// Launch
// ---------------------------------------------------------------------------
extern "C" void kernel_launch(void* const* d_in, const int* in_sizes, int n_in,
                              void* d_out, int out_size) {
    const float* features  = (const float*)d_in[0];
    const float* codebooks = (const float*)d_in[1];
    const float* Wq        = (const float*)d_in[2];
    const float* bq        = (const float*)d_in[3];
    const float* Wout      = (const float*)d_in[4];
    const float* bout      = (const float*)d_in[5];
    float* out = (float*)d_out;

    float* Qb;  cudaGetSymbolAddress((void**)&Qb,  g_Q);
    float* Gb;  cudaGetSymbolAddress((void**)&Gb,  g_G);
    int* idxP;  cudaGetSymbolAddress((void**)&idxP, g_idx);
    int* cntP;  cudaGetSymbolAddress((void**)&cntP, g_counts);
    float* dP;  cudaGetSymbolAddress((void**)&dP,  g_delta);

    zero_counts_k<<<16, 512>>>(cntP);
    delta_k<<<VV, 512>>>(codebooks, dP);
    sgemm_bt<<<dim3(8, 128), 256>>>(features, Wq, bq, Qb);
    fused_vq<<<TT, 512>>>(Qb, codebooks, dP, Gb, idxP, cntP);
    sgemm_bt<<<dim3(8, 128), 256>>>(Gb, Wout, bout, out);
    targets_k<<<(MROWS + 255) / 256, 256>>>(idxP, out);
    loss_k<<<1, 512>>>(cntP, out);
}

// round 5
// speedup vs baseline: 2.3417x; 1.6973x over previous
#include <cuda_runtime.h>
#include <cstdint>

// ---------------------------------------------------------------------------
// GumbelVectorQuantizer forward, GB300.
// B=8, T=2048, D=1024, V=16, K=512, d=64.
// ---------------------------------------------------------------------------

#define BB   8
#define TT   2048
#define DD   1024
#define VV   16
#define KK   512
#define DG   64
#define MROWS (BB * TT)          // 16384

#define OUT_QUANT   0
#define OUT_TARGETS (MROWS * DD)            // 16777216
#define OUT_LOSS    (MROWS * DD + MROWS)    // 16793600

// Scratch (device globals: allocation-free contract)
__device__ float g_Q[MROWS * DD];    // q = features @ Wq^T + bq
__device__ float g_G[MROWS * DD];    // gathered codebook rows
__device__ int   g_idx[MROWS * VV];  // argmax indices
__device__ int   g_counts[VV * KK];  // codebook usage counts
__device__ float g_delta[VV];        // per-group safe score window

// ===========================================================================
// Helpers
// ===========================================================================
__device__ __forceinline__ uint32_t smem_to_u32(const void* p) {
    uint32_t a;
    asm("{ .reg .u64 t; cvta.to.shared.u64 t, %1; cvt.u32.u64 %0, t; }"
        : "=r"(a) : "l"(p));
    return a;
}
__device__ __forceinline__ void cp16(uint32_t dst, const void* src) {
    asm volatile("cp.async.cg.shared.global [%0], [%1], 16;"
                 :: "r"(dst), "l"(src) : "memory");
}
#define CP_COMMIT() asm volatile("cp.async.commit_group;" ::: "memory")
#define CP_WAIT1()  asm volatile("cp.async.wait_group 1;" ::: "memory")
#define CP_WAIT0()  asm volatile("cp.async.wait_group 0;" ::: "memory")

__device__ __forceinline__ uint32_t tf32_hi(float a) {
    float r;
    asm("cvt.rna.tf32.f32 %0, %1;" : "=f"(r) : "f"(a));
    return __float_as_uint(r);
}

__device__ __forceinline__ void mma_tf32(float* c, const uint32_t* a,
                                         uint32_t b0, uint32_t b1) {
    asm volatile(
        "mma.sync.aligned.m16n8k8.row.col.f32.tf32.tf32.f32 "
        "{%0,%1,%2,%3}, {%4,%5,%6,%7}, {%8,%9}, {%0,%1,%2,%3};"
        : "+f"(c[0]), "+f"(c[1]), "+f"(c[2]), "+f"(c[3])
        : "r"(a[0]), "r"(a[1]), "r"(a[2]), "r"(a[3]), "r"(b0), "r"(b1));
}

// ===========================================================================
// TF32 tensor-core GEMM: C[M][1024] = A[M][1024] @ W[1024][1024]^T + bias
// tile 128x128, 256 threads (8 warps, 64x32 warp tiles), BK=32,
// cp.async double buffer, XOR-swizzled smem.
// SPLIT3: 3xTF32 (fp32-accurate) vs single TF32.
// ===========================================================================
#define GSM_STAGE 8192                 // floats per stage (A 4096 + B 4096)
#define GSM_BYTES (2 * GSM_STAGE * 4)  // 65536

template <bool SPLIT3>
__global__ __launch_bounds__(256)
void gemm_mma(const float* __restrict__ A, const float* __restrict__ W,
              const float* __restrict__ bias, float* __restrict__ C) {
    extern __shared__ float smemf[];
    const int tid = threadIdx.x;
    const int lane = tid & 31;
    const int wid = tid >> 5;
    const int m0 = blockIdx.y * 128;
    const int n0 = blockIdx.x * 128;

    const int lr = tid >> 1;          // load row 0..127
    const int lq = (tid & 1) * 4;     // float4 idx base 0 or 4
    const uint32_t sb = smem_to_u32(smemf);
    const float* Ab = A + (size_t)(m0 + lr) * DD;
    const float* Wb = W + (size_t)(n0 + lr) * DD;
    // swizzled byte offset of this thread's float4 slots (row lr, q)
    uint32_t soff[4];
#pragma unroll
    for (int j = 0; j < 4; j++) {
        int q = lq + j;
        soff[j] = (uint32_t)(lr * 32 + ((q * 4) ^ ((lr & 7) * 4))) * 4u;
    }

    const int gr = lane >> 2;   // 0..7
    const int gc = lane & 3;    // 0..3
    const int m0w = (wid & 1) * 64;
    const int n0w = (wid >> 1) * 32;

    float acc[4][4][4];
#pragma unroll
    for (int mi = 0; mi < 4; mi++)
#pragma unroll
        for (int ni = 0; ni < 4; ni++)
#pragma unroll
            for (int r = 0; r < 4; r++) acc[mi][ni][r] = 0.0f;

    // ---- prologue: chunk 0 into stage 0
#pragma unroll
    for (int j = 0; j < 4; j++) {
        cp16(sb + soff[j], Ab + lq * 4 + j * 4);
        cp16(sb + 16384 + soff[j], Wb + lq * 4 + j * 4);
    }
    CP_COMMIT();

    for (int i = 0; i < 32; i++) {
        const int s = i & 1;
        if (i < 31) {
            const uint32_t st = sb + (s ^ 1) * 32768;
            const int ko = (i + 1) * 32 + lq * 4;
#pragma unroll
            for (int j = 0; j < 4; j++) {
                cp16(st + soff[j], Ab + ko + j * 4);
                cp16(st + 16384 + soff[j], Wb + ko + j * 4);
            }
            CP_COMMIT();
            CP_WAIT1();
        } else {
            CP_WAIT0();
        }
        __syncthreads();

        const float* As = smemf + s * GSM_STAGE;
        const float* Bs = As + 4096;
#pragma unroll
        for (int kk = 0; kk < 32; kk += 8) {
            const int swz = gr * 4;
            const int c0 = (kk + gc) ^ swz;
            const int c1 = (kk + gc + 4) ^ swz;
            // B fragments (4 n-subtiles)
            uint32_t bh[4][2], bl[4][2];
#pragma unroll
            for (int ni = 0; ni < 4; ni++) {
                const int n = n0w + ni * 8 + gr;
                float b0 = Bs[n * 32 + c0];
                float b1 = Bs[n * 32 + c1];
                bh[ni][0] = tf32_hi(b0);
                bh[ni][1] = tf32_hi(b1);
                if (SPLIT3) {
                    bl[ni][0] = tf32_hi(b0 - __uint_as_float(bh[ni][0]));
                    bl[ni][1] = tf32_hi(b1 - __uint_as_float(bh[ni][1]));
                }
            }
#pragma unroll
            for (int mi = 0; mi < 4; mi++) {
                const int r0 = m0w + mi * 16 + gr;
                float a0 = As[r0 * 32 + c0];
                float a1 = As[(r0 + 8) * 32 + c0];
                float a2 = As[r0 * 32 + c1];
                float a3 = As[(r0 + 8) * 32 + c1];
                uint32_t ah[4], al[4];
                ah[0] = tf32_hi(a0); ah[1] = tf32_hi(a1);
                ah[2] = tf32_hi(a2); ah[3] = tf32_hi(a3);
                if (SPLIT3) {
                    al[0] = tf32_hi(a0 - __uint_as_float(ah[0]));
                    al[1] = tf32_hi(a1 - __uint_as_float(ah[1]));
                    al[2] = tf32_hi(a2 - __uint_as_float(ah[2]));
                    al[3] = tf32_hi(a3 - __uint_as_float(ah[3]));
                }
#pragma unroll
                for (int ni = 0; ni < 4; ni++) {
                    mma_tf32(acc[mi][ni], ah, bh[ni][0], bh[ni][1]);
                    if (SPLIT3) {
                        mma_tf32(acc[mi][ni], ah, bl[ni][0], bl[ni][1]);
                        mma_tf32(acc[mi][ni], al, bh[ni][0], bh[ni][1]);
                    }
                }
            }
        }
        __syncthreads();
    }

    // epilogue: C = acc + bias
#pragma unroll
    for (int mi = 0; mi < 4; mi++) {
#pragma unroll
        for (int ni = 0; ni < 4; ni++) {
            const int row = m0 + m0w + mi * 16 + gr;
            const int col = n0 + n0w + ni * 8 + gc * 2;
            const float bx = bias[col], by = bias[col + 1];
            float2 v0 = make_float2(acc[mi][ni][0] + bx, acc[mi][ni][1] + by);
            float2 v1 = make_float2(acc[mi][ni][2] + bx, acc[mi][ni][3] + by);
            *(float2*)(C + (size_t)row * DD + col) = v0;
            *(float2*)(C + (size_t)(row + 8) * DD + col) = v1;
        }
    }
}

// ---------------------------------------------------------------------------
// Threefry2x32, JAX partitionable path, key = (0, 42).
// ---------------------------------------------------------------------------
__device__ __forceinline__ uint32_t rotl32(uint32_t x, int r) {
    return __funnelshift_l(x, x, r);
}
__device__ __forceinline__ void tf_round(uint32_t& x0, uint32_t& x1, int r) {
    x0 += x1;
    x1 = rotl32(x1, r);
    x1 ^= x0;
}
__device__ __forceinline__ uint32_t tf_bits(uint32_t i) {
    const uint32_t ks0 = 0u;
    const uint32_t ks1 = 42u;
    const uint32_t ks2 = 0x1BD11BDAu ^ ks0 ^ ks1;
    uint32_t x0 = 0u + ks0;
    uint32_t x1 = i + ks1;
    tf_round(x0, x1, 13); tf_round(x0, x1, 15); tf_round(x0, x1, 26); tf_round(x0, x1, 6);
    x0 += ks1; x1 += ks2 + 1u;
    tf_round(x0, x1, 17); tf_round(x0, x1, 29); tf_round(x0, x1, 16); tf_round(x0, x1, 24);
    x0 += ks2; x1 += ks0 + 2u;
    tf_round(x0, x1, 13); tf_round(x0, x1, 15); tf_round(x0, x1, 26); tf_round(x0, x1, 6);
    x0 += ks0; x1 += ks1 + 3u;
    tf_round(x0, x1, 17); tf_round(x0, x1, 29); tf_round(x0, x1, 16); tf_round(x0, x1, 24);
    x0 += ks1; x1 += ks2 + 4u;
    tf_round(x0, x1, 13); tf_round(x0, x1, 15); tf_round(x0, x1, 26); tf_round(x0, x1, 6);
    x0 += ks2; x1 += ks0 + 5u;
    return x0 ^ x1;
}

__device__ __forceinline__ float gumbel_from_ubits(uint32_t ub) {
    float u = __uint_as_float(0x3f800000u | ub) - 1.0f;
    return -logf(-logf(u + 1e-8f) + 1e-8f);
}

// ---------------------------------------------------------------------------
// delta_k: per-v safe window  Delta_v = 2*max_k ||c_k|| + margin
// ---------------------------------------------------------------------------
__global__ void delta_k(const float* __restrict__ cbk, float* __restrict__ gd) {
    __shared__ float red[16];
    const int v = blockIdx.x;
    const int k = threadIdx.x;
    const int lane = k & 31, w = k >> 5;
    const float* crow = cbk + ((size_t)(v * KK + k)) * DG;
    float s = 0.0f;
#pragma unroll
    for (int d = 0; d < DG; d += 4) {
        float4 c = *(const float4*)(crow + d);
        s += c.x * c.x + c.y * c.y + c.z * c.z + c.w * c.w;
    }
#pragma unroll
    for (int o = 16; o; o >>= 1) s = fmaxf(s, __shfl_xor_sync(0xffffffffu, s, o));
    if (lane == 0) red[w] = s;
    __syncthreads();
    if (k == 0) {
        float m = 0.0f;
#pragma unroll
        for (int i = 0; i < 16; i++) m = fmaxf(m, red[i]);
        gd[v] = 2.0f * sqrtf(m) + 0.05f;
    }
}

// ---------------------------------------------------------------------------
// Fused: threefry bits -> integer argmax -> candidate window -> exact scores
// ---------------------------------------------------------------------------
#define CAP 4096

__global__ __launch_bounds__(512, 2)
void fused_vq(const float* __restrict__ Q, const float* __restrict__ cbk,
              const float* __restrict__ gdelta,
              float* __restrict__ G, int* __restrict__ idxOut,
              int* __restrict__ counts) {
    __shared__ uint32_t ub[8][KK];
    __shared__ uint32_t cand[CAP];
    __shared__ int scnt;
    __shared__ unsigned long long sbest[8];
    __shared__ uint32_t sthr[8];

    const int t = blockIdx.x;
    const int tid = threadIdx.x;
    const int lane = tid & 31;
    const int w = tid >> 5;
    const int k = tid;

    for (int v = 0; v < VV; v++) {
        if (tid < 8) sbest[tid] = 0ull;
        if (tid == 0) scnt = 0;

        uint32_t r[8];
        const uint32_t base = (uint32_t)t * 8192u + (uint32_t)v * 512u + (uint32_t)k;
#pragma unroll
        for (int b = 0; b < 8; b++) {
            uint32_t bits = tf_bits(base + ((uint32_t)b << 24));
            r[b] = bits >> 9;
            ub[b][k] = r[b];
        }
        __syncthreads();

        if (w < 8) {
            uint32_t m = 0u;
#pragma unroll
            for (int j = 0; j < 16; j++) m = max(m, ub[w][lane + 32 * j]);
#pragma unroll
            for (int o = 16; o; o >>= 1)
                m = max(m, __shfl_xor_sync(0xffffffffu, m, o));
            if (lane == 0) {
                float gmax = gumbel_from_ubits(m);
                float glo = gmax - gdelta[v];
                float ulo = expf(-(expf(-glo) - 1e-8f)) - 1e-8f;
                int it = (int)floorf(ulo * 8388608.0f) - 16;
                sthr[w] = (uint32_t)max(it, 0);
            }
        }
        __syncthreads();

#pragma unroll
        for (int b = 0; b < 8; b++) {
            if (r[b] >= sthr[b]) {
                int p = atomicAdd(&scnt, 1);
                cand[p] = ((uint32_t)b << 16) | (uint32_t)k;
            }
        }
        __syncthreads();

        const int n = scnt;
        for (int c = w; c < n; c += 16) {
            const uint32_t e = cand[c];
            const int b = (int)(e >> 16);
            const int kc = (int)(e & 0xffffu);
            const float* qrow = Q + ((size_t)(b * TT + t)) * DD + v * DG;
            const float* crow = cbk + ((size_t)(v * KK + kc)) * DG;
            float q0 = qrow[lane], q1 = qrow[lane + 32];
            float c0 = crow[lane], c1 = crow[lane + 32];
            float qc = q0 * c0 + q1 * c1;
            float q2 = q0 * q0 + q1 * q1;
            float c2 = c0 * c0 + c1 * c1;
#pragma unroll
            for (int o = 16; o; o >>= 1) {
                qc += __shfl_xor_sync(0xffffffffu, qc, o);
                q2 += __shfl_xor_sync(0xffffffffu, q2, o);
                c2 += __shfl_xor_sync(0xffffffffu, c2, o);
            }
            if (lane == 0) {
                float dist = sqrtf(fmaxf(q2 + c2 - 2.0f * qc, 0.0f));
                float g = gumbel_from_ubits(ub[b][kc]);
                float s = g - dist;
                uint32_t sbits = __float_as_uint(s);
                uint32_t os = (sbits & 0x80000000u) ? ~sbits : (sbits | 0x80000000u);
                unsigned long long key =
                    ((unsigned long long)os << 32) | (uint32_t)(511 - kc);
                atomicMax(&sbest[b], key);
            }
        }
        __syncthreads();

        if (w < 8) {
            const int b = w;
            const int kw = 511 - (int)(sbest[b] & 0xffffffffu);
            const float* crow = cbk + ((size_t)(v * KK + kw)) * DG;
            float* grow = G + ((size_t)(b * TT + t)) * DD + v * DG;
            grow[lane]      = crow[lane];
            grow[lane + 32] = crow[lane + 32];
            if (lane == 0) {
                idxOut[(b * TT + t) * VV + v] = kw;
                atomicAdd(&counts[v * KK + kw], 1);
            }
        }
        __syncthreads();
    }
}

// ---------------------------------------------------------------------------
// Small kernels
// ---------------------------------------------------------------------------
__global__ void zero_counts_k(int* __restrict__ counts) {
    int i = blockIdx.x * blockDim.x + threadIdx.x;
    if (i < VV * KK) counts[i] = 0;
}

__global__ void targets_k(const int* __restrict__ idxIn, float* __restrict__ out) {
    int i = blockIdx.x * blockDim.x + threadIdx.x;
    if (i < MROWS) {
        int s = 0;
#pragma unroll
        for (int v = 0; v < VV; v++) s += idxIn[i * VV + v] * (v * KK);
        out[OUT_TARGETS + i] = (float)s;
    }
}

__global__ void loss_k(const int* __restrict__ counts, float* __restrict__ out) {
    __shared__ float ent_s[VV];
    const int tid = threadIdx.x, lane = tid & 31, w = tid >> 5;
    if (w < VV) {
        float tot = 0.0f;
        for (int kk = lane; kk < KK; kk += 32) tot += (float)counts[w * KK + kk];
#pragma unroll
        for (int o = 16; o; o >>= 1) tot += __shfl_xor_sync(0xffffffffu, tot, o);
        float inv = 1.0f / tot;
        float pl = 0.0f;
        for (int kk = lane; kk < KK; kk += 32) {
            float p = (float)counts[w * KK + kk] * inv;
            pl += p * logf(p + 1e-8f);
        }
#pragma unroll
        for (int o = 16; o; o >>= 1) pl += __shfl_xor_sync(0xffffffffu, pl, o);
        if (lane == 0) ent_s[w] = -pl;
    }
    __syncthreads();
    if (tid == 0) {
        float lk = logf(512.0f);
        float acc = 0.0f;
#pragma unroll
        for (int v = 0; v < VV; v++) acc += ent_s[v] / lk;
        float diversity = -(acc / (float)VV);
        out[OUT_LOSS] = 0.1f * diversity;
    }
}

// ---------------------------------------------------------------------------
// Launch
// ---------------------------------------------------------------------------
extern "C" void kernel_launch(void* const* d_in, const int* in_sizes, int n_in,
                              void* d_out, int out_size) {
    const float* features  = (const float*)d_in[0];
    const float* codebooks = (const float*)d_in[1];
    const float* Wq        = (const float*)d_in[2];
    const float* bq        = (const float*)d_in[3];
    const float* Wout      = (const float*)d_in[4];
    const float* bout      = (const float*)d_in[5];
    float* out = (float*)d_out;

    float* Qb;  cudaGetSymbolAddress((void**)&Qb,  g_Q);
    float* Gb;  cudaGetSymbolAddress((void**)&Gb,  g_G);
    int* idxP;  cudaGetSymbolAddress((void**)&idxP, g_idx);
    int* cntP;  cudaGetSymbolAddress((void**)&cntP, g_counts);
    float* dP;  cudaGetSymbolAddress((void**)&dP,  g_delta);

    cudaFuncSetAttribute(gemm_mma<true>,
                         cudaFuncAttributeMaxDynamicSharedMemorySize, GSM_BYTES);
    cudaFuncSetAttribute(gemm_mma<false>,
                         cudaFuncAttributeMaxDynamicSharedMemorySize, GSM_BYTES);

    zero_counts_k<<<16, 512>>>(cntP);
    delta_k<<<VV, 512>>>(codebooks, dP);
    gemm_mma<true><<<dim3(8, 128), 256, GSM_BYTES>>>(features, Wq, bq, Qb);
    fused_vq<<<TT, 512>>>(Qb, codebooks, dP, Gb, idxP, cntP);
    gemm_mma<false><<<dim3(8, 128), 256, GSM_BYTES>>>(Gb, Wout, bout, out);
    targets_k<<<(MROWS + 255) / 256, 256>>>(idxP, out);
    loss_k<<<1, 512>>>(cntP, out);
}

// round 6
// speedup vs baseline: 2.8921x; 1.2351x over previous
#include <cuda_runtime.h>
#include <cstdint>

// ---------------------------------------------------------------------------
// GumbelVectorQuantizer forward, GB300.
// B=8, T=2048, D=1024, V=16, K=512, d=64.
// ---------------------------------------------------------------------------

#define BB   8
#define TT   2048
#define DD   1024
#define VV   16
#define KK   512
#define DG   64
#define MROWS (BB * TT)          // 16384

#define OUT_QUANT   0
#define OUT_TARGETS (MROWS * DD)            // 16777216
#define OUT_LOSS    (MROWS * DD + MROWS)    // 16793600

// Scratch (device globals: allocation-free contract)
__device__ float g_Q[MROWS * DD];        // q = features @ Wq^T + bq
__device__ float g_P[VV * KK * DD];      // P[v][k][:] = codebooks[v][k] @ Wout_v^T (+bout at v=0)
__device__ int   g_idx[MROWS * VV];      // argmax indices
__device__ int   g_counts[VV * KK];      // codebook usage counts
__device__ float g_delta[VV];            // per-group safe score window

// ===========================================================================
// Helpers
// ===========================================================================
__device__ __forceinline__ uint32_t smem_to_u32(const void* p) {
    uint32_t a;
    asm("{ .reg .u64 t; cvta.to.shared.u64 t, %1; cvt.u32.u64 %0, t; }"
        : "=r"(a) : "l"(p));
    return a;
}
__device__ __forceinline__ void cp16(uint32_t dst, const void* src) {
    asm volatile("cp.async.cg.shared.global [%0], [%1], 16;"
                 :: "r"(dst), "l"(src) : "memory");
}
#define CP_COMMIT() asm volatile("cp.async.commit_group;" ::: "memory")
#define CP_WAIT1()  asm volatile("cp.async.wait_group 1;" ::: "memory")
#define CP_WAIT0()  asm volatile("cp.async.wait_group 0;" ::: "memory")

__device__ __forceinline__ uint32_t tf32_hi(float a) {
    float r;
    asm("cvt.rna.tf32.f32 %0, %1;" : "=f"(r) : "f"(a));
    return __float_as_uint(r);
}

__device__ __forceinline__ void mma_tf32(float* c, const uint32_t* a,
                                         uint32_t b0, uint32_t b1) {
    asm volatile(
        "mma.sync.aligned.m16n8k8.row.col.f32.tf32.tf32.f32 "
        "{%0,%1,%2,%3}, {%4,%5,%6,%7}, {%8,%9}, {%0,%1,%2,%3};"
        : "+f"(c[0]), "+f"(c[1]), "+f"(c[2]), "+f"(c[3])
        : "r"(a[0]), "r"(a[1]), "r"(a[2]), "r"(a[3]), "r"(b0), "r"(b1));
}

// ===========================================================================
// 3xTF32 tensor-core GEMM: C[M][1024] = A[M][1024] @ W[1024][1024]^T + bias
// (fp32-accurate; used for the Wq projection only)
// ===========================================================================
#define GSM_STAGE 8192                 // floats per stage (A 4096 + B 4096)
#define GSM_BYTES (2 * GSM_STAGE * 4)  // 65536

__global__ __launch_bounds__(256)
void gemm_mma3(const float* __restrict__ A, const float* __restrict__ W,
               const float* __restrict__ bias, float* __restrict__ C) {
    extern __shared__ float smemf[];
    const int tid = threadIdx.x;
    const int lane = tid & 31;
    const int wid = tid >> 5;
    const int m0 = blockIdx.y * 128;
    const int n0 = blockIdx.x * 128;

    const int lr = tid >> 1;
    const int lq = (tid & 1) * 4;
    const uint32_t sb = smem_to_u32(smemf);
    const float* Ab = A + (size_t)(m0 + lr) * DD;
    const float* Wb = W + (size_t)(n0 + lr) * DD;
    uint32_t soff[4];
#pragma unroll
    for (int j = 0; j < 4; j++) {
        int q = lq + j;
        soff[j] = (uint32_t)(lr * 32 + ((q * 4) ^ ((lr & 7) * 4))) * 4u;
    }

    const int gr = lane >> 2;
    const int gc = lane & 3;
    const int m0w = (wid & 1) * 64;
    const int n0w = (wid >> 1) * 32;

    float acc[4][4][4];
#pragma unroll
    for (int mi = 0; mi < 4; mi++)
#pragma unroll
        for (int ni = 0; ni < 4; ni++)
#pragma unroll
            for (int r = 0; r < 4; r++) acc[mi][ni][r] = 0.0f;

#pragma unroll
    for (int j = 0; j < 4; j++) {
        cp16(sb + soff[j], Ab + lq * 4 + j * 4);
        cp16(sb + 16384 + soff[j], Wb + lq * 4 + j * 4);
    }
    CP_COMMIT();

    for (int i = 0; i < 32; i++) {
        const int s = i & 1;
        if (i < 31) {
            const uint32_t st = sb + (s ^ 1) * 32768;
            const int ko = (i + 1) * 32 + lq * 4;
#pragma unroll
            for (int j = 0; j < 4; j++) {
                cp16(st + soff[j], Ab + ko + j * 4);
                cp16(st + 16384 + soff[j], Wb + ko + j * 4);
            }
            CP_COMMIT();
            CP_WAIT1();
        } else {
            CP_WAIT0();
        }
        __syncthreads();

        const float* As = smemf + s * GSM_STAGE;
        const float* Bs = As + 4096;
#pragma unroll
        for (int kk = 0; kk < 32; kk += 8) {
            const int swz = gr * 4;
            const int c0 = (kk + gc) ^ swz;
            const int c1 = (kk + gc + 4) ^ swz;
            uint32_t bh[4][2], bl[4][2];
#pragma unroll
            for (int ni = 0; ni < 4; ni++) {
                const int n = n0w + ni * 8 + gr;
                float b0 = Bs[n * 32 + c0];
                float b1 = Bs[n * 32 + c1];
                bh[ni][0] = tf32_hi(b0);
                bh[ni][1] = tf32_hi(b1);
                bl[ni][0] = tf32_hi(b0 - __uint_as_float(bh[ni][0]));
                bl[ni][1] = tf32_hi(b1 - __uint_as_float(bh[ni][1]));
            }
#pragma unroll
            for (int mi = 0; mi < 4; mi++) {
                const int r0 = m0w + mi * 16 + gr;
                float a0 = As[r0 * 32 + c0];
                float a1 = As[(r0 + 8) * 32 + c0];
                float a2 = As[r0 * 32 + c1];
                float a3 = As[(r0 + 8) * 32 + c1];
                uint32_t ah[4], al[4];
                ah[0] = tf32_hi(a0); ah[1] = tf32_hi(a1);
                ah[2] = tf32_hi(a2); ah[3] = tf32_hi(a3);
                al[0] = tf32_hi(a0 - __uint_as_float(ah[0]));
                al[1] = tf32_hi(a1 - __uint_as_float(ah[1]));
                al[2] = tf32_hi(a2 - __uint_as_float(ah[2]));
                al[3] = tf32_hi(a3 - __uint_as_float(ah[3]));
#pragma unroll
                for (int ni = 0; ni < 4; ni++) {
                    mma_tf32(acc[mi][ni], ah, bh[ni][0], bh[ni][1]);
                    mma_tf32(acc[mi][ni], ah, bl[ni][0], bl[ni][1]);
                    mma_tf32(acc[mi][ni], al, bh[ni][0], bh[ni][1]);
                }
            }
        }
        __syncthreads();
    }

#pragma unroll
    for (int mi = 0; mi < 4; mi++) {
#pragma unroll
        for (int ni = 0; ni < 4; ni++) {
            const int row = m0 + m0w + mi * 16 + gr;
            const int col = n0 + n0w + ni * 8 + gc * 2;
            const float bx = bias[col], by = bias[col + 1];
            float2 v0 = make_float2(acc[mi][ni][0] + bx, acc[mi][ni][1] + by);
            float2 v1 = make_float2(acc[mi][ni][2] + bx, acc[mi][ni][3] + by);
            *(float2*)(C + (size_t)row * DD + col) = v0;
            *(float2*)(C + (size_t)(row + 8) * DD + col) = v1;
        }
    }
}

// ===========================================================================
// pmat: P[v][k][n] = sum_d codebooks[v][k][d] * Wout[n][v*64+d]  (+bout[n] @ v==0)
// grid (8 ntiles, 8 ktiles, 16 v), 256 threads.
// ===========================================================================
__global__ __launch_bounds__(256)
void pmat_k(const float* __restrict__ cbk, const float* __restrict__ Wout,
            const float* __restrict__ bout, float* __restrict__ P) {
    __shared__ float Ct[64][65];
    __shared__ float Wt[128][65];
    const int v = blockIdx.z;
    const int k0 = blockIdx.y * 64;
    const int n0 = blockIdx.x * 128;
    const int tid = threadIdx.x;

    for (int i = tid; i < 64 * 16; i += 256) {
        int rr = i >> 4, dq = (i & 15) * 4;
        float4 c = *(const float4*)(cbk + (((size_t)v * KK + k0 + rr) << 6) + dq);
        Ct[rr][dq + 0] = c.x; Ct[rr][dq + 1] = c.y;
        Ct[rr][dq + 2] = c.z; Ct[rr][dq + 3] = c.w;
    }
    for (int i = tid; i < 128 * 16; i += 256) {
        int rr = i >> 4, dq = (i & 15) * 4;
        float4 wv = *(const float4*)(Wout + (size_t)(n0 + rr) * DD + v * DG + dq);
        Wt[rr][dq + 0] = wv.x; Wt[rr][dq + 1] = wv.y;
        Wt[rr][dq + 2] = wv.z; Wt[rr][dq + 3] = wv.w;
    }
    __syncthreads();

    const int ks = (tid >> 4) * 4;
    const int ns = (tid & 15) * 8;
    float acc[4][8];
#pragma unroll
    for (int i = 0; i < 4; i++)
#pragma unroll
        for (int j = 0; j < 8; j++) acc[i][j] = 0.0f;

#pragma unroll 8
    for (int d = 0; d < 64; d++) {
        float cv[4], wv[8];
#pragma unroll
        for (int i = 0; i < 4; i++) cv[i] = Ct[ks + i][d];
#pragma unroll
        for (int j = 0; j < 8; j++) wv[j] = Wt[ns + j][d];
#pragma unroll
        for (int i = 0; i < 4; i++)
#pragma unroll
            for (int j = 0; j < 8; j++)
                acc[i][j] = fmaf(cv[i], wv[j], acc[i][j]);
    }

#pragma unroll
    for (int i = 0; i < 4; i++) {
        float* prow = P + (((size_t)v * KK + k0 + ks + i) << 10) + n0 + ns;
        float4 o0, o1;
        float b0 = 0, b1 = 0, b2 = 0, b3 = 0, b4 = 0, b5 = 0, b6 = 0, b7 = 0;
        if (v == 0) {
            b0 = bout[n0 + ns + 0]; b1 = bout[n0 + ns + 1];
            b2 = bout[n0 + ns + 2]; b3 = bout[n0 + ns + 3];
            b4 = bout[n0 + ns + 4]; b5 = bout[n0 + ns + 5];
            b6 = bout[n0 + ns + 6]; b7 = bout[n0 + ns + 7];
        }
        o0.x = acc[i][0] + b0; o0.y = acc[i][1] + b1;
        o0.z = acc[i][2] + b2; o0.w = acc[i][3] + b3;
        o1.x = acc[i][4] + b4; o1.y = acc[i][5] + b5;
        o1.z = acc[i][6] + b6; o1.w = acc[i][7] + b7;
        *(float4*)(prow + 0) = o0;
        *(float4*)(prow + 4) = o1;
    }
}

// ---------------------------------------------------------------------------
// Threefry2x32, JAX partitionable path, key = (0, 42).
// ---------------------------------------------------------------------------
__device__ __forceinline__ uint32_t rotl32(uint32_t x, int r) {
    return __funnelshift_l(x, x, r);
}
__device__ __forceinline__ void tf_round(uint32_t& x0, uint32_t& x1, int r) {
    x0 += x1;
    x1 = rotl32(x1, r);
    x1 ^= x0;
}
__device__ __forceinline__ uint32_t tf_bits(uint32_t i) {
    const uint32_t ks0 = 0u;
    const uint32_t ks1 = 42u;
    const uint32_t ks2 = 0x1BD11BDAu ^ ks0 ^ ks1;
    uint32_t x0 = 0u + ks0;
    uint32_t x1 = i + ks1;
    tf_round(x0, x1, 13); tf_round(x0, x1, 15); tf_round(x0, x1, 26); tf_round(x0, x1, 6);
    x0 += ks1; x1 += ks2 + 1u;
    tf_round(x0, x1, 17); tf_round(x0, x1, 29); tf_round(x0, x1, 16); tf_round(x0, x1, 24);
    x0 += ks2; x1 += ks0 + 2u;
    tf_round(x0, x1, 13); tf_round(x0, x1, 15); tf_round(x0, x1, 26); tf_round(x0, x1, 6);
    x0 += ks0; x1 += ks1 + 3u;
    tf_round(x0, x1, 17); tf_round(x0, x1, 29); tf_round(x0, x1, 16); tf_round(x0, x1, 24);
    x0 += ks1; x1 += ks2 + 4u;
    tf_round(x0, x1, 13); tf_round(x0, x1, 15); tf_round(x0, x1, 26); tf_round(x0, x1, 6);
    x0 += ks2; x1 += ks0 + 5u;
    return x0 ^ x1;
}

__device__ __forceinline__ float gumbel_from_ubits(uint32_t ub) {
    float u = __uint_as_float(0x3f800000u | ub) - 1.0f;
    return -logf(-logf(u + 1e-8f) + 1e-8f);
}

// ---------------------------------------------------------------------------
// delta_k: per-v safe window  Delta_v = 2*max_k ||c_k|| + margin
// ---------------------------------------------------------------------------
__global__ void delta_k(const float* __restrict__ cbk, float* __restrict__ gd) {
    __shared__ float red[16];
    const int v = blockIdx.x;
    const int k = threadIdx.x;
    const int lane = k & 31, w = k >> 5;
    const float* crow = cbk + ((size_t)(v * KK + k)) * DG;
    float s = 0.0f;
#pragma unroll
    for (int d = 0; d < DG; d += 4) {
        float4 c = *(const float4*)(crow + d);
        s += c.x * c.x + c.y * c.y + c.z * c.z + c.w * c.w;
    }
#pragma unroll
    for (int o = 16; o; o >>= 1) s = fmaxf(s, __shfl_xor_sync(0xffffffffu, s, o));
    if (lane == 0) red[w] = s;
    __syncthreads();
    if (k == 0) {
        float m = 0.0f;
#pragma unroll
        for (int i = 0; i < 16; i++) m = fmaxf(m, red[i]);
        gd[v] = 2.0f * sqrtf(m) + 0.05f;
    }
}

// ---------------------------------------------------------------------------
// fused_vq2: one warp per (b,t,v) group. No shared, no block syncs.
// blockIdx.x = v*2048 + t; warp = batch b. 256 threads = 8 warps.
// ---------------------------------------------------------------------------
__global__ __launch_bounds__(256)
void fused_vq2(const float* __restrict__ Q, const float* __restrict__ cbk,
               const float* __restrict__ gdelta,
               int* __restrict__ idxOut, int* __restrict__ counts) {
    const int v = blockIdx.x >> 11;
    const int t = blockIdx.x & 2047;
    const int b = threadIdx.x >> 5;
    const int lane = threadIdx.x & 31;

    // 1) threefry bits for this lane's 16 k values (raw 32-bit), track max
    const uint32_t base = (uint32_t)t * 8192u + (uint32_t)v * 512u +
                          ((uint32_t)b << 24) + (uint32_t)lane;
    uint32_t r[16];
    uint32_t m = 0u;
#pragma unroll
    for (int j = 0; j < 16; j++) {
        r[j] = tf_bits(base + 32u * j);
        m = max(m, r[j]);
    }
#pragma unroll
    for (int o = 16; o; o >>= 1) m = max(m, __shfl_xor_sync(0xffffffffu, m, o));

    // 2) threshold from the integer max (uniform computation warp-wide)
    const float gmax = gumbel_from_ubits(m >> 9);
    const float glo = gmax - gdelta[v];
    const float ulo = expf(-(expf(-glo) - 1e-8f)) - 1e-8f;
    const int it = (int)floorf(ulo * 8388608.0f) - 16;
    const uint32_t thr = ((uint32_t)max(it, 0)) << 9;   // compare in raw-bit space

    // 3) q row + q2
    const float* qrow = Q + ((size_t)(b * TT + t)) * DD + v * DG;
    const float q0 = qrow[lane], q1 = qrow[lane + 32];
    float q2 = q0 * q0 + q1 * q1;
#pragma unroll
    for (int o = 16; o; o >>= 1) q2 += __shfl_xor_sync(0xffffffffu, q2, o);

    // 4) candidates, ascending k; strict-greater keeps earliest (tie-break)
    float bestS = -3.4e38f;
    int bestK = 0;
#pragma unroll
    for (int j = 0; j < 16; j++) {
        unsigned mask = __ballot_sync(0xffffffffu, r[j] >= thr);
        while (mask) {
            const int src = __ffs(mask) - 1;
            mask &= mask - 1;
            const int kc = 32 * j + src;
            const uint32_t ubc = __shfl_sync(0xffffffffu, r[j], src) >> 9;
            const float* crow = cbk + (((size_t)v * KK + kc) << 6);
            const float c0 = crow[lane], c1 = crow[lane + 32];
            float qc = q0 * c0 + q1 * c1;
            float c2 = c0 * c0 + c1 * c1;
#pragma unroll
            for (int o = 16; o; o >>= 1) {
                qc += __shfl_xor_sync(0xffffffffu, qc, o);
                c2 += __shfl_xor_sync(0xffffffffu, c2, o);
            }
            const float dist = sqrtf(fmaxf(q2 + c2 - 2.0f * qc, 0.0f));
            const float s = gumbel_from_ubits(ubc) - dist;
            if (s > bestS) { bestS = s; bestK = kc; }
        }
    }

    if (lane == 0) {
        idxOut[(b * TT + t) * VV + v] = bestK;
        atomicAdd(&counts[v * KK + bestK], 1);
    }
}

// ---------------------------------------------------------------------------
// gather_sum: quantized[b,t] = sum_v P[v][idx_v]  (bout folded into P[0]);
// also emits targets. One block (128 thr) per token row.
// ---------------------------------------------------------------------------
__global__ __launch_bounds__(128)
void gather_sum(const float* __restrict__ P, const int* __restrict__ idx,
                float* __restrict__ out) {
    __shared__ int sidx[VV];
    const int row = blockIdx.x;
    const int tid = threadIdx.x;
    if (tid < VV) sidx[tid] = idx[row * VV + tid];
    __syncthreads();

    const int n = tid * 8;
    float4 a0 = make_float4(0.f, 0.f, 0.f, 0.f);
    float4 a1 = make_float4(0.f, 0.f, 0.f, 0.f);
#pragma unroll
    for (int v = 0; v < VV; v++) {
        const float* p = P + ((((size_t)v << 9) + sidx[v]) << 10) + n;
        float4 x = *(const float4*)(p + 0);
        float4 y = *(const float4*)(p + 4);
        a0.x += x.x; a0.y += x.y; a0.z += x.z; a0.w += x.w;
        a1.x += y.x; a1.y += y.y; a1.z += y.z; a1.w += y.w;
    }
    float* o = out + (size_t)row * DD + n;
    *(float4*)(o + 0) = a0;
    *(float4*)(o + 4) = a1;

    if (tid == 0) {
        int s = 0;
#pragma unroll
        for (int v = 0; v < VV; v++) s += sidx[v] * (v * KK);
        out[OUT_TARGETS + row] = (float)s;
    }
}

// ---------------------------------------------------------------------------
// Small kernels
// ---------------------------------------------------------------------------
__global__ void zero_counts_k(int* __restrict__ counts) {
    int i = blockIdx.x * blockDim.x + threadIdx.x;
    if (i < VV * KK) counts[i] = 0;
}

__global__ void loss_k(const int* __restrict__ counts, float* __restrict__ out) {
    __shared__ float ent_s[VV];
    const int tid = threadIdx.x, lane = tid & 31, w = tid >> 5;
    if (w < VV) {
        float tot = 0.0f;
        for (int kk = lane; kk < KK; kk += 32) tot += (float)counts[w * KK + kk];
#pragma unroll
        for (int o = 16; o; o >>= 1) tot += __shfl_xor_sync(0xffffffffu, tot, o);
        float inv = 1.0f / tot;
        float pl = 0.0f;
        for (int kk = lane; kk < KK; kk += 32) {
            float p = (float)counts[w * KK + kk] * inv;
            pl += p * logf(p + 1e-8f);
        }
#pragma unroll
        for (int o = 16; o; o >>= 1) pl += __shfl_xor_sync(0xffffffffu, pl, o);
        if (lane == 0) ent_s[w] = -pl;
    }
    __syncthreads();
    if (tid == 0) {
        float lk = logf(512.0f);
        float acc = 0.0f;
#pragma unroll
        for (int v = 0; v < VV; v++) acc += ent_s[v] / lk;
        float diversity = -(acc / (float)VV);
        out[OUT_LOSS] = 0.1f * diversity;
    }
}

// ---------------------------------------------------------------------------
// Launch
// ---------------------------------------------------------------------------
extern "C" void kernel_launch(void* const* d_in, const int* in_sizes, int n_in,
                              void* d_out, int out_size) {
    const float* features  = (const float*)d_in[0];
    const float* codebooks = (const float*)d_in[1];
    const float* Wq        = (const float*)d_in[2];
    const float* bq        = (const float*)d_in[3];
    const float* Wout      = (const float*)d_in[4];
    const float* bout      = (const float*)d_in[5];
    float* out = (float*)d_out;

    float* Qb;  cudaGetSymbolAddress((void**)&Qb,  g_Q);
    float* Pb;  cudaGetSymbolAddress((void**)&Pb,  g_P);
    int* idxP;  cudaGetSymbolAddress((void**)&idxP, g_idx);
    int* cntP;  cudaGetSymbolAddress((void**)&cntP, g_counts);
    float* dP;  cudaGetSymbolAddress((void**)&dP,  g_delta);

    cudaFuncSetAttribute(gemm_mma3,
                         cudaFuncAttributeMaxDynamicSharedMemorySize, GSM_BYTES);

    zero_counts_k<<<16, 512>>>(cntP);
    delta_k<<<VV, 512>>>(codebooks, dP);
    pmat_k<<<dim3(8, 8, VV), 256>>>(codebooks, Wout, bout, Pb);
    gemm_mma3<<<dim3(8, 128), 256, GSM_BYTES>>>(features, Wq, bq, Qb);
    fused_vq2<<<VV * TT, 256>>>(Qb, codebooks, dP, idxP, cntP);
    gather_sum<<<MROWS, 128>>>(Pb, idxP, out);
    loss_k<<<1, 512>>>(cntP, out);
}